// round 5
// baseline (speedup 1.0000x reference)
#include <cuda_runtime.h>
#include <math.h>

#define B_ROWS 32768
#define IN_DIM 1024
#define HID    128
#define LAT    64
#define NCODE  4096

// Scratch (no cudaMalloc allowed): hidden activations reused for h and h2.
__device__ __align__(16) float g_h[(size_t)B_ROWS * HID];
__device__ float g_e2[NCODE];
__device__ float g_loss;

// ---------------------------------------------------------------------------
// Generic tiled SGEMM with fused bias + activation.
// C[M,N] = act(A[M,K] @ B[K,N] + bias[N])
// BM=BN=64, BK=16, 256 threads, 4x4 micro-tile per thread.
// ACT: 0 = none, 1 = relu, 2 = sigmoid
// ---------------------------------------------------------------------------
template<int ACT>
__global__ void gemm_bias_act(const float* __restrict__ A,
                              const float* __restrict__ Bm,
                              const float* __restrict__ bias,
                              float* __restrict__ C,
                              int M, int N, int K) {
    __shared__ float As[16][68];  // [k][m], padded
    __shared__ float Bs[16][68];  // [k][n], padded

    const int tid = threadIdx.x;
    const int tx = tid & 15;
    const int ty = tid >> 4;
    const int bm = blockIdx.y * 64;
    const int bn = blockIdx.x * 64;

    float acc[4][4];
#pragma unroll
    for (int i = 0; i < 4; i++)
#pragma unroll
        for (int j = 0; j < 4; j++) acc[i][j] = 0.f;

    const int ar  = tid >> 2;          // 0..63 A-tile row
    const int ac4 = (tid & 3) << 2;    // 0,4,8,12 k offset
    const int brk = tid >> 4;          // 0..15 B-tile k row
    const int bcn = (tid & 15) << 2;   // 0..60 n offset

    for (int k0 = 0; k0 < K; k0 += 16) {
        float4 va = *(const float4*)(A + (size_t)(bm + ar) * K + k0 + ac4);
        As[ac4 + 0][ar] = va.x;
        As[ac4 + 1][ar] = va.y;
        As[ac4 + 2][ar] = va.z;
        As[ac4 + 3][ar] = va.w;
        float4 vb = *(const float4*)(Bm + (size_t)(k0 + brk) * N + bn + bcn);
        *(float4*)&Bs[brk][bcn] = vb;
        __syncthreads();

#pragma unroll
        for (int k = 0; k < 16; k++) {
            float4 a4 = *(const float4*)&As[k][ty << 2];
            float4 b4 = *(const float4*)&Bs[k][tx << 2];
            float av[4] = {a4.x, a4.y, a4.z, a4.w};
            float bv[4] = {b4.x, b4.y, b4.z, b4.w};
#pragma unroll
            for (int i = 0; i < 4; i++)
#pragma unroll
                for (int j = 0; j < 4; j++)
                    acc[i][j] = fmaf(av[i], bv[j], acc[i][j]);
        }
        __syncthreads();
    }

#pragma unroll
    for (int i = 0; i < 4; i++) {
        const int row = bm + (ty << 2) + i;
        float o[4];
#pragma unroll
        for (int j = 0; j < 4; j++) {
            const int col = bn + (tx << 2) + j;
            float v = acc[i][j] + bias[col];
            if (ACT == 1) v = fmaxf(v, 0.f);
            else if (ACT == 2) v = 1.f / (1.f + expf(-v));
            o[j] = v;
        }
        *(float4*)(C + (size_t)row * N + bn + (tx << 2)) =
            make_float4(o[0], o[1], o[2], o[3]);
    }
}

// ---------------------------------------------------------------------------
// Codebook squared norms: e2[c] = sum_d cb[c][d]^2
// ---------------------------------------------------------------------------
__global__ void e2_kernel(const float* __restrict__ cb) {
    int c = blockIdx.x * blockDim.x + threadIdx.x;
    if (c < NCODE) {
        const float4* p = (const float4*)(cb + (size_t)c * LAT);
        float s = 0.f;
#pragma unroll
        for (int i = 0; i < 16; i++) {
            float4 v = p[i];
            s = fmaf(v.x, v.x, s);
            s = fmaf(v.y, v.y, s);
            s = fmaf(v.z, v.z, s);
            s = fmaf(v.w, v.w, s);
        }
        g_e2[c] = s;
    }
}

__global__ void zero_kernel() { g_loss = 0.f; }

// ---------------------------------------------------------------------------
// Fused VQ. Reference computes (fp32, left-assoc):
//     d2 = (x2 - 2*(latent@cb^T)) + e2
// The large per-row constant x2 QUANTIZES the comparison values at ulp(x2);
// we reproduce that rounding exactly (incl. tie collapse -> first-index win)
// to match jnp.argmin. __f*_rn intrinsics prevent FMA contraction in the
// final combine.
//
// Parallelism: 2 threads per row. tid<128 ("half 0") scans codes [0,2048),
// tid>=128 ("half 1") scans [2048,4096). Since every half-0 index < every
// half-1 index, the combine uses strict (s1 < s0): equal-s ties resolve to
// half 0, exactly matching first-index argmin. Within a half the ascending
// scan with (s < best) keeps the first minimum.
//
// Writes quantized_st = latent + (q - latent) with the reference's rounding,
// and accumulates sum((q - latent)^2) into g_loss.
// Block: 256 threads handle 128 rows. 32 KB shared stages 2x64-code tiles.
// ---------------------------------------------------------------------------
__global__ void vq_kernel(const float* __restrict__ latent,
                          const float* __restrict__ cb,
                          float* __restrict__ quant) {
    __shared__ float4 sC[2][64 * 16];  // 2 halves x 64 codes x 64 dims = 32 KB
    __shared__ float  sE[2][64];
    __shared__ float  sBestS[128];
    __shared__ int    sBestI[128];

    const int tid  = threadIdx.x;
    const int rloc = tid & 127;       // row within block
    const int half = tid >> 7;        // 0 or 1
    const int row  = blockIdx.x * 128 + rloc;
    const int cbase = half * (NCODE / 2);

    float4 lat[16];
    const float4* lp = (const float4*)(latent + (size_t)row * LAT);
#pragma unroll
    for (int i = 0; i < 16; i++) lat[i] = lp[i];

    // x2 = sum(latent^2) for this row (identical in both halves)
    float x2 = 0.f;
#pragma unroll
    for (int i = 0; i < 16; i++) {
        float4 a = lat[i];
        x2 = fmaf(a.x, a.x, x2);
        x2 = fmaf(a.y, a.y, x2);
        x2 = fmaf(a.z, a.z, x2);
        x2 = fmaf(a.w, a.w, x2);
    }

    float best = 3.4e38f;
    int   bi   = 0;

    for (int it = 0; it < NCODE / 2 / 64; it++) {
        // Stage 128 codes: half h's tile = codes [h*2048 + it*64, +64)
        // 128 codes x 16 float4 = 2048 float4; 256 threads -> 8 each.
        {
            const int t0 = tid * 8;
            const int h  = t0 >> 10;            // which half's tile
            const int off = t0 & 1023;          // float4 offset within tile
            const float4* gsrc =
                (const float4*)(cb + (size_t)(h * (NCODE / 2) + it * 64) * LAT);
#pragma unroll
            for (int u = 0; u < 8; u++) sC[h][off + u] = gsrc[off + u];
        }
        if (tid < 128) {
            const int h = tid >> 6, c = tid & 63;
            sE[h][c] = g_e2[h * (NCODE / 2) + it * 64 + c];
        }
        __syncthreads();

#pragma unroll 2
        for (int c = 0; c < 64; c++) {
            const float4* cp = &sC[half][c * 16];
            float d0 = 0.f, d1 = 0.f, d2 = 0.f, d3 = 0.f;
#pragma unroll
            for (int g = 0; g < 16; g++) {
                float4 a = lat[g];
                float4 b = cp[g];
                d0 = fmaf(a.x, b.x, d0);
                d1 = fmaf(a.y, b.y, d1);
                d2 = fmaf(a.z, b.z, d2);
                d3 = fmaf(a.w, b.w, d3);
            }
            float m = __fadd_rn(__fadd_rn(d0, d1), __fadd_rn(d2, d3));
            // s = (x2 - 2*m) + e2, rounded exactly like the reference
            float t = __fsub_rn(x2, __fmul_rn(2.0f, m));
            float s = __fadd_rn(t, sE[half][c]);
            if (s < best) { best = s; bi = cbase + it * 64 + c; }
        }
        __syncthreads();
    }

    // Cross-half combine: half 1 publishes, half 0 resolves (strict <).
    if (half == 1) { sBestS[rloc] = best; sBestI[rloc] = bi; }
    __syncthreads();
    if (half == 1) return;
    if (sBestS[rloc] < best) { best = sBestS[rloc]; bi = sBestI[rloc]; }

    // quantized_st = latent + (q - latent)  (reference's straight-through
    // expression; its rounding differs from plain q at ~ulp(latent)).
    const float4* qp = (const float4*)(cb + (size_t)bi * LAT);
    float4* outq = (float4*)(quant + (size_t)row * LAT);
    float sumsq = 0.f;
#pragma unroll
    for (int i = 0; i < 16; i++) {
        float4 q = qp[i];
        float dx = __fsub_rn(q.x, lat[i].x);
        float dy = __fsub_rn(q.y, lat[i].y);
        float dz = __fsub_rn(q.z, lat[i].z);
        float dw = __fsub_rn(q.w, lat[i].w);
        float4 st;
        st.x = __fadd_rn(lat[i].x, dx);
        st.y = __fadd_rn(lat[i].y, dy);
        st.z = __fadd_rn(lat[i].z, dz);
        st.w = __fadd_rn(lat[i].w, dw);
        outq[i] = st;
        sumsq += dx * dx + dy * dy + dz * dz + dw * dw;
    }

    // warp reduce + one atomic per warp (only warps 0..3 reach here)
#pragma unroll
    for (int off = 16; off > 0; off >>= 1)
        sumsq += __shfl_down_sync(0xffffffffu, sumsq, off);
    if ((tid & 31) == 0) atomicAdd(&g_loss, sumsq);
}

// loss = q_latent_loss + 0.25 * e_latent_loss; both terms are the same number
// mean((q - latent)^2) = m, combined as m + 0.25*m like the reference.
__global__ void finalize_kernel(float* __restrict__ loss_out) {
    float m = g_loss / (float)((size_t)B_ROWS * LAT);
    *loss_out = __fadd_rn(m, __fmul_rn(0.25f, m));
}

// ---------------------------------------------------------------------------
extern "C" void kernel_launch(void* const* d_in, const int* in_sizes, int n_in,
                              void* d_out, int out_size) {
    const float* x      = (const float*)d_in[0];
    const float* enc_w1 = (const float*)d_in[1];
    const float* enc_b1 = (const float*)d_in[2];
    const float* enc_w2 = (const float*)d_in[3];
    const float* enc_b2 = (const float*)d_in[4];
    const float* cb     = (const float*)d_in[5];
    const float* dec_w1 = (const float*)d_in[6];
    const float* dec_b1 = (const float*)d_in[7];
    const float* dec_w2 = (const float*)d_in[8];
    const float* dec_b2 = (const float*)d_in[9];

    float* out    = (float*)d_out;
    float* latent = out;
    float* quant  = out + (size_t)B_ROWS * LAT;
    float* recon  = out + (size_t)2 * B_ROWS * LAT;
    float* loss   = out + (size_t)2 * B_ROWS * LAT + (size_t)B_ROWS * IN_DIM;

    float* hbuf = nullptr;
    cudaGetSymbolAddress((void**)&hbuf, g_h);

    zero_kernel<<<1, 1>>>();
    e2_kernel<<<NCODE / 256, 256>>>(cb);

    // encoder layer 1: h = relu(x @ enc_w1 + enc_b1)   [32768,128]
    gemm_bias_act<1><<<dim3(HID / 64, B_ROWS / 64), 256>>>(
        x, enc_w1, enc_b1, hbuf, B_ROWS, HID, IN_DIM);

    // encoder layer 2: latent = relu(h @ enc_w2 + enc_b2)   [32768,64]
    gemm_bias_act<1><<<dim3(LAT / 64, B_ROWS / 64), 256>>>(
        hbuf, enc_w2, enc_b2, latent, B_ROWS, LAT, HID);

    // vector quantization + straight-through output + loss accumulation
    vq_kernel<<<B_ROWS / 128, 256>>>(latent, cb, quant);

    // decoder layer 1: h2 = relu(quantized_st @ dec_w1 + dec_b1)   [32768,128]
    gemm_bias_act<1><<<dim3(HID / 64, B_ROWS / 64), 256>>>(
        quant, dec_w1, dec_b1, hbuf, B_ROWS, HID, LAT);

    // decoder layer 2: recon = sigmoid(h2 @ dec_w2 + dec_b2)   [32768,1024]
    gemm_bias_act<2><<<dim3(IN_DIM / 64, B_ROWS / 64), 256>>>(
        hbuf, dec_w2, dec_b2, recon, B_ROWS, IN_DIM, HID);

    finalize_kernel<<<1, 1>>>(loss);
}

// round 6
// speedup vs baseline: 1.0400x; 1.0400x over previous
#include <cuda_runtime.h>
#include <math.h>

#define B_ROWS 32768
#define IN_DIM 1024
#define HID    128
#define LAT    64
#define NCODE  4096

// Scratch (no cudaMalloc allowed): hidden activations reused for h and h2.
__device__ __align__(16) float g_h[(size_t)B_ROWS * HID];
__device__ float g_e2[NCODE];
__device__ float g_loss;

// ---------------------------------------------------------------------------
// Packed fp32x2 helpers (Blackwell FFMA2 — two IEEE fp32 FMAs per issue slot;
// lanes are bit-identical to scalar FFMA, so numerics are unchanged).
// ---------------------------------------------------------------------------
__device__ __forceinline__ void ffma2(unsigned long long& d,
                                      unsigned long long a,
                                      unsigned long long b) {
    asm("fma.rn.f32x2 %0, %1, %2, %0;" : "+l"(d) : "l"(a), "l"(b));
}
__device__ __forceinline__ unsigned long long pack2(float lo, float hi) {
    unsigned long long r;
    asm("mov.b64 %0, {%1, %2};" : "=l"(r)
        : "r"(__float_as_uint(lo)), "r"(__float_as_uint(hi)));
    return r;
}
__device__ __forceinline__ float2 unpack2(unsigned long long p) {
    unsigned int lo, hi;
    asm("mov.b64 {%0, %1}, %2;" : "=r"(lo), "=r"(hi) : "l"(p));
    return make_float2(__uint_as_float(lo), __uint_as_float(hi));
}

union F4U2 { float4 f4; ulonglong2 u2; };

// ---------------------------------------------------------------------------
// Generic tiled SGEMM with fused bias + activation.
// C[M,N] = act(A[M,K] @ B[K,N] + bias[N])
// BM=BN=64, BK=16, 256 threads, 4x4 micro-tile per thread.
// Inner product via FFMA2: acc lanes packed over j-pairs; each lane executes
// exactly the same FMA sequence as the scalar version (bit-identical output).
// ACT: 0 = none, 1 = relu, 2 = sigmoid
// ---------------------------------------------------------------------------
template<int ACT>
__global__ void gemm_bias_act(const float* __restrict__ A,
                              const float* __restrict__ Bm,
                              const float* __restrict__ bias,
                              float* __restrict__ C,
                              int M, int N, int K) {
    __shared__ float As[16][68];  // [k][m], padded
    __shared__ float Bs[16][68];  // [k][n], padded

    const int tid = threadIdx.x;
    const int tx = tid & 15;
    const int ty = tid >> 4;
    const int bm = blockIdx.y * 64;
    const int bn = blockIdx.x * 64;

    // accp[i][0] lanes = (acc[i][0], acc[i][1]); accp[i][1] = (acc[i][2], acc[i][3])
    unsigned long long accp[4][2];
#pragma unroll
    for (int i = 0; i < 4; i++) { accp[i][0] = 0ull; accp[i][1] = 0ull; }

    const int ar  = tid >> 2;          // 0..63 A-tile row
    const int ac4 = (tid & 3) << 2;    // 0,4,8,12 k offset
    const int brk = tid >> 4;          // 0..15 B-tile k row
    const int bcn = (tid & 15) << 2;   // 0..60 n offset

    for (int k0 = 0; k0 < K; k0 += 16) {
        float4 va = *(const float4*)(A + (size_t)(bm + ar) * K + k0 + ac4);
        As[ac4 + 0][ar] = va.x;
        As[ac4 + 1][ar] = va.y;
        As[ac4 + 2][ar] = va.z;
        As[ac4 + 3][ar] = va.w;
        float4 vb = *(const float4*)(Bm + (size_t)(k0 + brk) * N + bn + bcn);
        *(float4*)&Bs[brk][bcn] = vb;
        __syncthreads();

#pragma unroll
        for (int k = 0; k < 16; k++) {
            float4 a4 = *(const float4*)&As[k][ty << 2];
            F4U2 b; b.f4 = *(const float4*)&Bs[k][tx << 2];
            float av[4] = {a4.x, a4.y, a4.z, a4.w};
#pragma unroll
            for (int i = 0; i < 4; i++) {
                unsigned long long ai = pack2(av[i], av[i]);
                ffma2(accp[i][0], ai, b.u2.x);
                ffma2(accp[i][1], ai, b.u2.y);
            }
        }
        __syncthreads();
    }

#pragma unroll
    for (int i = 0; i < 4; i++) {
        const int row = bm + (ty << 2) + i;
        float2 p0 = unpack2(accp[i][0]);
        float2 p1 = unpack2(accp[i][1]);
        float accr[4] = {p0.x, p0.y, p1.x, p1.y};
        float o[4];
#pragma unroll
        for (int j = 0; j < 4; j++) {
            const int col = bn + (tx << 2) + j;
            float v = accr[j] + bias[col];
            if (ACT == 1) v = fmaxf(v, 0.f);
            else if (ACT == 2) v = 1.f / (1.f + expf(-v));
            o[j] = v;
        }
        *(float4*)(C + (size_t)row * N + bn + (tx << 2)) =
            make_float4(o[0], o[1], o[2], o[3]);
    }
}

// ---------------------------------------------------------------------------
// Codebook squared norms: e2[c] = sum_d cb[c][d]^2
// ---------------------------------------------------------------------------
__global__ void e2_kernel(const float* __restrict__ cb) {
    int c = blockIdx.x * blockDim.x + threadIdx.x;
    if (c < NCODE) {
        const float4* p = (const float4*)(cb + (size_t)c * LAT);
        float s = 0.f;
#pragma unroll
        for (int i = 0; i < 16; i++) {
            float4 v = p[i];
            s = fmaf(v.x, v.x, s);
            s = fmaf(v.y, v.y, s);
            s = fmaf(v.z, v.z, s);
            s = fmaf(v.w, v.w, s);
        }
        g_e2[c] = s;
    }
}

__global__ void zero_kernel() { g_loss = 0.f; }

// ---------------------------------------------------------------------------
// Fused VQ. Reference computes (fp32, left-assoc):
//     d2 = (x2 - 2*(latent@cb^T)) + e2
// The large per-row constant x2 QUANTIZES the comparison values at ulp(x2);
// we reproduce that rounding exactly (incl. tie collapse -> first-index win)
// to match jnp.argmin.
//
// FFMA2 packing: dxy lanes accumulate (x,y) products, dzw lanes (z,w) — lane
// k of each packed accumulator runs EXACTLY the scalar d0..d3 chains of the
// R5-passing kernel, so m and s are bit-identical to the validated version.
//
// Parallelism: 2 threads per row (halves of the codebook); strict (s1 < s0)
// cross-half combine preserves first-index argmin semantics since all half-0
// indices are smaller.
// ---------------------------------------------------------------------------
__global__ void vq_kernel(const float* __restrict__ latent,
                          const float* __restrict__ cb,
                          float* __restrict__ quant) {
    __shared__ float4 sC[2][64 * 16];  // 2 halves x 64 codes x 64 dims = 32 KB
    __shared__ float  sE[2][64];
    __shared__ float  sBestS[128];
    __shared__ int    sBestI[128];

    const int tid  = threadIdx.x;
    const int rloc = tid & 127;       // row within block
    const int half = tid >> 7;        // 0 or 1
    const int row  = blockIdx.x * 128 + rloc;
    const int cbase = half * (NCODE / 2);

    // latent row as 16 packed-pair-pairs: latp[i].x = (x,y), latp[i].y = (z,w)
    ulonglong2 latp[16];
    const ulonglong2* lp = (const ulonglong2*)(latent + (size_t)row * LAT);
#pragma unroll
    for (int i = 0; i < 16; i++) latp[i] = lp[i];

    // x2 = sum(latent^2), same fmaf chain order as the validated kernel
    float x2 = 0.f;
#pragma unroll
    for (int i = 0; i < 16; i++) {
        float2 p0 = unpack2(latp[i].x);
        float2 p1 = unpack2(latp[i].y);
        x2 = fmaf(p0.x, p0.x, x2);
        x2 = fmaf(p0.y, p0.y, x2);
        x2 = fmaf(p1.x, p1.x, x2);
        x2 = fmaf(p1.y, p1.y, x2);
    }

    float best = 3.4e38f;
    int   bi   = 0;

    for (int it = 0; it < NCODE / 2 / 64; it++) {
        // Stage 128 codes (64 per half): 2048 float4, 8 per thread.
        {
            const int t0 = tid * 8;
            const int h  = t0 >> 10;            // which half's tile
            const int off = t0 & 1023;          // float4 offset within tile
            const float4* gsrc =
                (const float4*)(cb + (size_t)(h * (NCODE / 2) + it * 64) * LAT);
#pragma unroll
            for (int u = 0; u < 8; u++) sC[h][off + u] = gsrc[off + u];
        }
        if (tid < 128) {
            const int h = tid >> 6, c = tid & 63;
            sE[h][c] = g_e2[h * (NCODE / 2) + it * 64 + c];
        }
        __syncthreads();

#pragma unroll 2
        for (int c = 0; c < 64; c++) {
            const ulonglong2* cp = (const ulonglong2*)&sC[half][c * 16];
            unsigned long long dxy = 0ull, dzw = 0ull;
#pragma unroll
            for (int g = 0; g < 16; g++) {
                ulonglong2 b = cp[g];
                ffma2(dxy, latp[g].x, b.x);
                ffma2(dzw, latp[g].y, b.y);
            }
            float2 v0 = unpack2(dxy);   // (d0, d1)
            float2 v1 = unpack2(dzw);   // (d2, d3)
            float m = __fadd_rn(__fadd_rn(v0.x, v0.y), __fadd_rn(v1.x, v1.y));
            // s = (x2 - 2*m) + e2, rounded exactly like the reference
            float t = __fsub_rn(x2, __fmul_rn(2.0f, m));
            float s = __fadd_rn(t, sE[half][c]);
            if (s < best) { best = s; bi = cbase + it * 64 + c; }
        }
        __syncthreads();
    }

    // Cross-half combine: half 1 publishes, half 0 resolves (strict <).
    if (half == 1) { sBestS[rloc] = best; sBestI[rloc] = bi; }
    __syncthreads();
    if (half == 1) return;
    if (sBestS[rloc] < best) { best = sBestS[rloc]; bi = sBestI[rloc]; }

    // quantized_st = latent + (q - latent)  (reference's straight-through
    // expression; its rounding differs from plain q at ~ulp(latent)).
    const float4* qp = (const float4*)(cb + (size_t)bi * LAT);
    float4* outq = (float4*)(quant + (size_t)row * LAT);
    float sumsq = 0.f;
#pragma unroll
    for (int i = 0; i < 16; i++) {
        float4 q = qp[i];
        float2 l0 = unpack2(latp[i].x);
        float2 l1 = unpack2(latp[i].y);
        float dx = __fsub_rn(q.x, l0.x);
        float dy = __fsub_rn(q.y, l0.y);
        float dz = __fsub_rn(q.z, l1.x);
        float dw = __fsub_rn(q.w, l1.y);
        float4 st;
        st.x = __fadd_rn(l0.x, dx);
        st.y = __fadd_rn(l0.y, dy);
        st.z = __fadd_rn(l1.x, dz);
        st.w = __fadd_rn(l1.y, dw);
        outq[i] = st;
        sumsq += dx * dx + dy * dy + dz * dz + dw * dw;
    }

    // warp reduce + one atomic per warp (only warps 0..3 reach here)
#pragma unroll
    for (int off = 16; off > 0; off >>= 1)
        sumsq += __shfl_down_sync(0xffffffffu, sumsq, off);
    if ((tid & 31) == 0) atomicAdd(&g_loss, sumsq);
}

// loss = q_latent_loss + 0.25 * e_latent_loss; both terms are the same number
// mean((q - latent)^2) = m, combined as m + 0.25*m like the reference.
__global__ void finalize_kernel(float* __restrict__ loss_out) {
    float m = g_loss / (float)((size_t)B_ROWS * LAT);
    *loss_out = __fadd_rn(m, __fmul_rn(0.25f, m));
}

// ---------------------------------------------------------------------------
extern "C" void kernel_launch(void* const* d_in, const int* in_sizes, int n_in,
                              void* d_out, int out_size) {
    const float* x      = (const float*)d_in[0];
    const float* enc_w1 = (const float*)d_in[1];
    const float* enc_b1 = (const float*)d_in[2];
    const float* enc_w2 = (const float*)d_in[3];
    const float* enc_b2 = (const float*)d_in[4];
    const float* cb     = (const float*)d_in[5];
    const float* dec_w1 = (const float*)d_in[6];
    const float* dec_b1 = (const float*)d_in[7];
    const float* dec_w2 = (const float*)d_in[8];
    const float* dec_b2 = (const float*)d_in[9];

    float* out    = (float*)d_out;
    float* latent = out;
    float* quant  = out + (size_t)B_ROWS * LAT;
    float* recon  = out + (size_t)2 * B_ROWS * LAT;
    float* loss   = out + (size_t)2 * B_ROWS * LAT + (size_t)B_ROWS * IN_DIM;

    float* hbuf = nullptr;
    cudaGetSymbolAddress((void**)&hbuf, g_h);

    zero_kernel<<<1, 1>>>();
    e2_kernel<<<NCODE / 256, 256>>>(cb);

    // encoder layer 1: h = relu(x @ enc_w1 + enc_b1)   [32768,128]
    gemm_bias_act<1><<<dim3(HID / 64, B_ROWS / 64), 256>>>(
        x, enc_w1, enc_b1, hbuf, B_ROWS, HID, IN_DIM);

    // encoder layer 2: latent = relu(h @ enc_w2 + enc_b2)   [32768,64]
    gemm_bias_act<1><<<dim3(LAT / 64, B_ROWS / 64), 256>>>(
        hbuf, enc_w2, enc_b2, latent, B_ROWS, LAT, HID);

    // vector quantization + straight-through output + loss accumulation
    vq_kernel<<<B_ROWS / 128, 256>>>(latent, cb, quant);

    // decoder layer 1: h2 = relu(quantized_st @ dec_w1 + dec_b1)   [32768,128]
    gemm_bias_act<1><<<dim3(HID / 64, B_ROWS / 64), 256>>>(
        quant, dec_w1, dec_b1, hbuf, B_ROWS, HID, LAT);

    // decoder layer 2: recon = sigmoid(h2 @ dec_w2 + dec_b2)   [32768,1024]
    gemm_bias_act<2><<<dim3(IN_DIM / 64, B_ROWS / 64), 256>>>(
        hbuf, dec_w2, dec_b2, recon, B_ROWS, IN_DIM, HID);

    finalize_kernel<<<1, 1>>>(loss);
}

// round 7
// speedup vs baseline: 1.1239x; 1.0807x over previous
#include <cuda_runtime.h>
#include <math.h>

#define B_ROWS 32768
#define IN_DIM 1024
#define HID    128
#define LAT    64
#define NCODE  4096

// Scratch (no cudaMalloc allowed): hidden activations reused for h and h2.
__device__ __align__(16) float g_h[(size_t)B_ROWS * HID];
__device__ float g_e2[NCODE];
__device__ float g_loss;

// ---------------------------------------------------------------------------
// Packed fp32x2 helpers (Blackwell FFMA2 — two IEEE fp32 FMAs per issue slot;
// lanes are bit-identical to scalar FFMA, so numerics are unchanged).
// ---------------------------------------------------------------------------
__device__ __forceinline__ void ffma2(unsigned long long& d,
                                      unsigned long long a,
                                      unsigned long long b) {
    asm("fma.rn.f32x2 %0, %1, %2, %0;" : "+l"(d) : "l"(a), "l"(b));
}
__device__ __forceinline__ unsigned long long pack2(float lo, float hi) {
    unsigned long long r;
    asm("mov.b64 %0, {%1, %2};" : "=l"(r)
        : "r"(__float_as_uint(lo)), "r"(__float_as_uint(hi)));
    return r;
}
__device__ __forceinline__ float2 unpack2(unsigned long long p) {
    unsigned int lo, hi;
    asm("mov.b64 {%0, %1}, %2;" : "=r"(lo), "=r"(hi) : "l"(p));
    return make_float2(__uint_as_float(lo), __uint_as_float(hi));
}

union F4U2 { float4 f4; ulonglong2 u2; };

// cp.async (LDGSTS) helpers
__device__ __forceinline__ void cp16(void* smem_dst, const void* gptr) {
    unsigned int s = (unsigned int)__cvta_generic_to_shared(smem_dst);
    asm volatile("cp.async.cg.shared.global [%0], [%1], 16;" :: "r"(s), "l"(gptr));
}
__device__ __forceinline__ void cp4(void* smem_dst, const void* gptr) {
    unsigned int s = (unsigned int)__cvta_generic_to_shared(smem_dst);
    asm volatile("cp.async.ca.shared.global [%0], [%1], 4;" :: "r"(s), "l"(gptr));
}
__device__ __forceinline__ void cp_commit() {
    asm volatile("cp.async.commit_group;");
}

// ---------------------------------------------------------------------------
// Tiled SGEMM with fused bias + activation, double-buffered smem.
// C[M,N] = act(A[M,K] @ B[K,N] + bias[N])
// BM=BN=64, BK=16, 256 threads, 4x4 micro-tile per thread, FFMA2 inner
// product (bit-identical lanes vs scalar). One __syncthreads per k0-iter;
// next tile's global loads prefetched into registers during compute.
// ACT: 0 = none, 1 = relu, 2 = sigmoid
// ---------------------------------------------------------------------------
template<int ACT>
__global__ void gemm_bias_act(const float* __restrict__ A,
                              const float* __restrict__ Bm,
                              const float* __restrict__ bias,
                              float* __restrict__ C,
                              int M, int N, int K) {
    __shared__ float As[2][16][68];  // [buf][k][m], padded
    __shared__ float Bs[2][16][68];  // [buf][k][n], padded

    const int tid = threadIdx.x;
    const int tx = tid & 15;
    const int ty = tid >> 4;
    const int bm = blockIdx.y * 64;
    const int bn = blockIdx.x * 64;

    unsigned long long accp[4][2];
#pragma unroll
    for (int i = 0; i < 4; i++) { accp[i][0] = 0ull; accp[i][1] = 0ull; }

    const int ar  = tid >> 2;          // 0..63 A-tile row
    const int ac4 = (tid & 3) << 2;    // 0,4,8,12 k offset
    const int brk = tid >> 4;          // 0..15 B-tile k row
    const int bcn = (tid & 15) << 2;   // 0..60 n offset

    const int nk = K >> 4;

    // preload tile 0
    {
        float4 va = *(const float4*)(A + (size_t)(bm + ar) * K + ac4);
        As[0][ac4 + 0][ar] = va.x;
        As[0][ac4 + 1][ar] = va.y;
        As[0][ac4 + 2][ar] = va.z;
        As[0][ac4 + 3][ar] = va.w;
        float4 vb = *(const float4*)(Bm + (size_t)brk * N + bn + bcn);
        *(float4*)&Bs[0][brk][bcn] = vb;
    }
    __syncthreads();

    for (int i = 0; i < nk; i++) {
        const int buf = i & 1;
        float4 va2, vb2;
        const bool more = (i + 1 < nk);
        if (more) {
            const int k0 = (i + 1) << 4;
            va2 = *(const float4*)(A + (size_t)(bm + ar) * K + k0 + ac4);
            vb2 = *(const float4*)(Bm + (size_t)(k0 + brk) * N + bn + bcn);
        }

#pragma unroll
        for (int k = 0; k < 16; k++) {
            float4 a4 = *(const float4*)&As[buf][k][ty << 2];
            F4U2 b; b.f4 = *(const float4*)&Bs[buf][k][tx << 2];
            float av[4] = {a4.x, a4.y, a4.z, a4.w};
#pragma unroll
            for (int ii = 0; ii < 4; ii++) {
                unsigned long long ai = pack2(av[ii], av[ii]);
                ffma2(accp[ii][0], ai, b.u2.x);
                ffma2(accp[ii][1], ai, b.u2.y);
            }
        }

        if (more) {
            const int nb = buf ^ 1;
            As[nb][ac4 + 0][ar] = va2.x;
            As[nb][ac4 + 1][ar] = va2.y;
            As[nb][ac4 + 2][ar] = va2.z;
            As[nb][ac4 + 3][ar] = va2.w;
            *(float4*)&Bs[nb][brk][bcn] = vb2;
        }
        __syncthreads();
    }

#pragma unroll
    for (int i = 0; i < 4; i++) {
        const int row = bm + (ty << 2) + i;
        float2 p0 = unpack2(accp[i][0]);
        float2 p1 = unpack2(accp[i][1]);
        float accr[4] = {p0.x, p0.y, p1.x, p1.y};
        float o[4];
#pragma unroll
        for (int j = 0; j < 4; j++) {
            const int col = bn + (tx << 2) + j;
            float v = accr[j] + bias[col];
            if (ACT == 1) v = fmaxf(v, 0.f);
            else if (ACT == 2) v = 1.f / (1.f + expf(-v));
            o[j] = v;
        }
        *(float4*)(C + (size_t)row * N + bn + (tx << 2)) =
            make_float4(o[0], o[1], o[2], o[3]);
    }
}

// ---------------------------------------------------------------------------
// Codebook squared norms: e2[c] = sum_d cb[c][d]^2   (+ zero g_loss)
// ---------------------------------------------------------------------------
__global__ void e2_kernel(const float* __restrict__ cb) {
    int c = blockIdx.x * blockDim.x + threadIdx.x;
    if (c == 0) g_loss = 0.f;
    if (c < NCODE) {
        const float4* p = (const float4*)(cb + (size_t)c * LAT);
        float s = 0.f;
#pragma unroll
        for (int i = 0; i < 16; i++) {
            float4 v = p[i];
            s = fmaf(v.x, v.x, s);
            s = fmaf(v.y, v.y, s);
            s = fmaf(v.z, v.z, s);
            s = fmaf(v.w, v.w, s);
        }
        g_e2[c] = s;
    }
}

// ---------------------------------------------------------------------------
// Fused VQ. Reference computes (fp32, left-assoc):
//     d2 = (x2 - 2*(latent@cb^T)) + e2
// The large per-row constant x2 QUANTIZES the comparison values at ulp(x2);
// we reproduce that rounding exactly (incl. tie collapse -> first-index win)
// to match jnp.argmin. Per-(row,code) FMA chains and the final combine are
// byte-identical to the validated R6 kernel.
//
// Pipeline: code tiles staged via cp.async into double-buffered smem; tile
// it+1 is in flight while tile it is scored (wait_group 1).
// Parallelism: 2 threads per row (codebook halves); strict (s1 < s0)
// cross-half combine preserves first-index argmin semantics.
// ---------------------------------------------------------------------------
__global__ void vq_kernel(const float* __restrict__ latent,
                          const float* __restrict__ cb,
                          float* __restrict__ quant) {
    __shared__ float4 sC[2][2][64 * 16];  // [buf][half][code*16] = 64 KB
    __shared__ float  sE[2][2][64];
    __shared__ float  sBestS[128];
    __shared__ int    sBestI[128];

    const int tid  = threadIdx.x;
    const int rloc = tid & 127;       // row within block
    const int half = tid >> 7;        // 0 or 1
    const int row  = blockIdx.x * 128 + rloc;
    const int cbase = half * (NCODE / 2);

    // staging geometry (all 256 threads move 8 float4 each = 128 codes)
    const int t0   = tid * 8;
    const int sh   = t0 >> 10;            // which half's tile this thread fills
    const int soff = t0 & 1023;           // float4 offset within tile

    // latent row as 16 packed-pair-pairs: latp[i].x = (x,y), latp[i].y = (z,w)
    ulonglong2 latp[16];
    const ulonglong2* lp = (const ulonglong2*)(latent + (size_t)row * LAT);
#pragma unroll
    for (int i = 0; i < 16; i++) latp[i] = lp[i];

    // x2 = sum(latent^2), same fmaf chain order as the validated kernel
    float x2 = 0.f;
#pragma unroll
    for (int i = 0; i < 16; i++) {
        float2 p0 = unpack2(latp[i].x);
        float2 p1 = unpack2(latp[i].y);
        x2 = fmaf(p0.x, p0.x, x2);
        x2 = fmaf(p0.y, p0.y, x2);
        x2 = fmaf(p1.x, p1.x, x2);
        x2 = fmaf(p1.y, p1.y, x2);
    }

    float best = 3.4e38f;
    int   bi   = 0;

    const int NIT = NCODE / 2 / 64;   // 32

    // stage tile 0 into buf 0
    {
        const float4* gsrc = (const float4*)(cb + (size_t)(sh * (NCODE / 2)) * LAT);
#pragma unroll
        for (int u = 0; u < 8; u++) cp16(&sC[0][sh][soff + u], gsrc + soff + u);
        if (tid < 128) {
            const int h = tid >> 6, c = tid & 63;
            cp4(&sE[0][h][c], &g_e2[h * (NCODE / 2) + c]);
        }
        cp_commit();
    }

    for (int it = 0; it < NIT; it++) {
        const int buf = it & 1;
        if (it + 1 < NIT) {
            // stage tile it+1 into the other buffer (overlaps compute below)
            const float4* gsrc =
                (const float4*)(cb + (size_t)(sh * (NCODE / 2) + (it + 1) * 64) * LAT);
#pragma unroll
            for (int u = 0; u < 8; u++) cp16(&sC[buf ^ 1][sh][soff + u], gsrc + soff + u);
            if (tid < 128) {
                const int h = tid >> 6, c = tid & 63;
                cp4(&sE[buf ^ 1][h][c], &g_e2[h * (NCODE / 2) + (it + 1) * 64 + c]);
            }
            cp_commit();
            asm volatile("cp.async.wait_group 1;");   // tile it done, it+1 in flight
        } else {
            asm volatile("cp.async.wait_group 0;");
        }
        __syncthreads();

#pragma unroll 2
        for (int c = 0; c < 64; c++) {
            const ulonglong2* cp = (const ulonglong2*)&sC[buf][half][c * 16];
            unsigned long long dxy = 0ull, dzw = 0ull;
#pragma unroll
            for (int g = 0; g < 16; g++) {
                ulonglong2 b = cp[g];
                ffma2(dxy, latp[g].x, b.x);
                ffma2(dzw, latp[g].y, b.y);
            }
            float2 v0 = unpack2(dxy);   // (d0, d1)
            float2 v1 = unpack2(dzw);   // (d2, d3)
            float m = __fadd_rn(__fadd_rn(v0.x, v0.y), __fadd_rn(v1.x, v1.y));
            // s = (x2 - 2*m) + e2, rounded exactly like the reference
            float t = __fsub_rn(x2, __fmul_rn(2.0f, m));
            float s = __fadd_rn(t, sE[buf][half][c]);
            if (s < best) { best = s; bi = cbase + it * 64 + c; }
        }
        __syncthreads();   // all reads of buf done before it gets re-staged
    }

    // Cross-half combine: half 1 publishes, half 0 resolves (strict <).
    if (half == 1) { sBestS[rloc] = best; sBestI[rloc] = bi; }
    __syncthreads();
    if (half == 1) return;
    if (sBestS[rloc] < best) { best = sBestS[rloc]; bi = sBestI[rloc]; }

    // quantized_st = latent + (q - latent)  (reference's straight-through
    // expression; its rounding differs from plain q at ~ulp(latent)).
    const float4* qp = (const float4*)(cb + (size_t)bi * LAT);
    float4* outq = (float4*)(quant + (size_t)row * LAT);
    float sumsq = 0.f;
#pragma unroll
    for (int i = 0; i < 16; i++) {
        float4 q = qp[i];
        float2 l0 = unpack2(latp[i].x);
        float2 l1 = unpack2(latp[i].y);
        float dx = __fsub_rn(q.x, l0.x);
        float dy = __fsub_rn(q.y, l0.y);
        float dz = __fsub_rn(q.z, l1.x);
        float dw = __fsub_rn(q.w, l1.y);
        float4 st;
        st.x = __fadd_rn(l0.x, dx);
        st.y = __fadd_rn(l0.y, dy);
        st.z = __fadd_rn(l1.x, dz);
        st.w = __fadd_rn(l1.y, dw);
        outq[i] = st;
        sumsq += dx * dx + dy * dy + dz * dz + dw * dw;
    }

    // warp reduce + one atomic per warp (only warps 0..3 reach here)
#pragma unroll
    for (int off = 16; off > 0; off >>= 1)
        sumsq += __shfl_down_sync(0xffffffffu, sumsq, off);
    if ((tid & 31) == 0) atomicAdd(&g_loss, sumsq);
}

// loss = q_latent_loss + 0.25 * e_latent_loss; both terms are the same number
// mean((q - latent)^2) = m, combined as m + 0.25*m like the reference.
__global__ void finalize_kernel(float* __restrict__ loss_out) {
    float m = g_loss / (float)((size_t)B_ROWS * LAT);
    *loss_out = __fadd_rn(m, __fmul_rn(0.25f, m));
}

// ---------------------------------------------------------------------------
extern "C" void kernel_launch(void* const* d_in, const int* in_sizes, int n_in,
                              void* d_out, int out_size) {
    const float* x      = (const float*)d_in[0];
    const float* enc_w1 = (const float*)d_in[1];
    const float* enc_b1 = (const float*)d_in[2];
    const float* enc_w2 = (const float*)d_in[3];
    const float* enc_b2 = (const float*)d_in[4];
    const float* cb     = (const float*)d_in[5];
    const float* dec_w1 = (const float*)d_in[6];
    const float* dec_b1 = (const float*)d_in[7];
    const float* dec_w2 = (const float*)d_in[8];
    const float* dec_b2 = (const float*)d_in[9];

    float* out    = (float*)d_out;
    float* latent = out;
    float* quant  = out + (size_t)B_ROWS * LAT;
    float* recon  = out + (size_t)2 * B_ROWS * LAT;
    float* loss   = out + (size_t)2 * B_ROWS * LAT + (size_t)B_ROWS * IN_DIM;

    float* hbuf = nullptr;
    cudaGetSymbolAddress((void**)&hbuf, g_h);

    e2_kernel<<<NCODE / 256, 256>>>(cb);

    // encoder layer 1: h = relu(x @ enc_w1 + enc_b1)   [32768,128]
    gemm_bias_act<1><<<dim3(HID / 64, B_ROWS / 64), 256>>>(
        x, enc_w1, enc_b1, hbuf, B_ROWS, HID, IN_DIM);

    // encoder layer 2: latent = relu(h @ enc_w2 + enc_b2)   [32768,64]
    gemm_bias_act<1><<<dim3(LAT / 64, B_ROWS / 64), 256>>>(
        hbuf, enc_w2, enc_b2, latent, B_ROWS, LAT, HID);

    // vector quantization + straight-through output + loss accumulation
    vq_kernel<<<B_ROWS / 128, 256>>>(latent, cb, quant);

    // decoder layer 1: h2 = relu(quantized_st @ dec_w1 + dec_b1)   [32768,128]
    gemm_bias_act<1><<<dim3(HID / 64, B_ROWS / 64), 256>>>(
        quant, dec_w1, dec_b1, hbuf, B_ROWS, HID, LAT);

    // decoder layer 2: recon = sigmoid(h2 @ dec_w2 + dec_b2)   [32768,1024]
    gemm_bias_act<2><<<dim3(IN_DIM / 64, B_ROWS / 64), 256>>>(
        hbuf, dec_w2, dec_b2, recon, B_ROWS, IN_DIM, HID);

    finalize_kernel<<<1, 1>>>(loss);
}